// round 8
// baseline (speedup 1.0000x reference)
#include <cuda_runtime.h>

#define N_    48
#define W_    16
#define X_    256
#define NW_   (N_ * W_)
#define AG    4                  // anchors per group
#define NG    (N_ / AG)          // 12 groups
#define NCH   12                 // column chunks
#define CPB   (NW_ / NCH)        // 64 columns per chunk
#define NWARP 16
#define BLK   (NWARP * 32)       // 512 threads
#define CPWRP (CPB / NWARP)      // 4 columns per warp
#define GRID  (NG * NCH)         // 144 blocks
#define INF_  1e30f
#define FULL  0xffffffffu

// Per-(anchor, chunk) partials
__device__ float    g_tsum[N_][NCH];
__device__ unsigned g_combo[N_][NCH];    // hard | (accu<<16)
__device__ float    g_sumNeg[N_][NCH];
__device__ float    g_minV[N_][NCH];
__device__ int      g_minI[N_][NCH];
// Per-anchor pos stats (single writer: block with c == g)
__device__ float    g_sumPos[N_];
__device__ float    g_maxV[N_];
__device__ int      g_maxI[N_];
__device__ int      g_count;             // zero-init; reset by finish block

__global__ void __launch_bounds__(BLK, 2) triplet_kernel(
    const float* __restrict__ emb,   // [N, W, X] f32
    const float* __restrict__ lab,   // [N, W]    f32 (0/1)
    float* __restrict__ out)         // [337]     f32
{
    const int bid  = blockIdx.x;
    const int g    = bid / NCH;            // anchor group (anchors 4g..4g+3)
    const int c    = bid % NCH;            // column chunk
    const int col0 = c * CPB;
    const int tid  = threadIdx.x;
    const int lane = tid & 31;
    const int warp = tid >> 5;
    const bool ownChunk = (c == g);        // group g's rows live in chunk g

    __shared__ __align__(16) float s_anchor[AG][X_];   // 4 KB
    __shared__ float    s_lab[AG * W_];
    __shared__ float    s_down[AG][W_];                // own-row distances
    __shared__ float    s_tsum[AG][NWARP];
    __shared__ unsigned s_combo[AG][NWARP];
    __shared__ float    s_sn[AG][NWARP], s_minv[AG][NWARP];
    __shared__ int      s_mini[AG][NWARP];
    __shared__ float    s_sp[AG][NWARP], s_maxv[AG][NWARP];
    __shared__ int      s_maxi[AG][NWARP];
    __shared__ int      s_last;

    // ---- anchors + labels into smem ----
    for (int k = tid; k < AG * X_; k += BLK) {
        const int a = k >> 8, x = k & (X_ - 1);
        s_anchor[a][x] = emb[((size_t)(g * AG + a) * W_) * X_ + x];
    }
    if (tid < AG * W_) s_lab[tid] = lab[g * AG * W_ + tid];
    __syncthreads();

    // ---- own-row distances: warp w handles own cols 4w..4w+3 ----
    float down[CPWRP];
    #pragma unroll
    for (int jj = 0; jj < CPWRP; jj++) {
        const int oc = warp * CPWRP + jj;        // 0..63 within group rows
        const float4* fo = reinterpret_cast<const float4*>(emb + (size_t)(g * CPB + oc) * X_);
        float4 va = fo[lane], vb = fo[lane + 32];
        const float4* ap = reinterpret_cast<const float4*>(s_anchor[oc >> 4]);
        float4 a1 = ap[lane], a2 = ap[lane + 32];
        float s = 0.f, d;
        d = a1.x - va.x; s = fmaf(d, d, s);
        d = a1.y - va.y; s = fmaf(d, d, s);
        d = a1.z - va.z; s = fmaf(d, d, s);
        d = a1.w - va.w; s = fmaf(d, d, s);
        d = a2.x - vb.x; s = fmaf(d, d, s);
        d = a2.y - vb.y; s = fmaf(d, d, s);
        d = a2.z - vb.z; s = fmaf(d, d, s);
        d = a2.w - vb.w; s = fmaf(d, d, s);
        down[jj] = s;
    }

    // ---- chunk distances: warp w owns cols col0+4w..+3, vs all 4 anchors ----
    float dist[AG][CPWRP];
    #pragma unroll
    for (int jj = 0; jj < CPWRP; jj++) {
        const int j = col0 + warp * CPWRP + jj;
        const float4* f = reinterpret_cast<const float4*>(emb + (size_t)j * X_);
        float4 va = f[lane], vb = f[lane + 32];
        #pragma unroll
        for (int a = 0; a < AG; a++) {
            const float4* ap = reinterpret_cast<const float4*>(s_anchor[a]);
            float4 a1 = ap[lane], a2 = ap[lane + 32];
            float s = 0.f, d;
            d = a1.x - va.x; s = fmaf(d, d, s);
            d = a1.y - va.y; s = fmaf(d, d, s);
            d = a1.z - va.z; s = fmaf(d, d, s);
            d = a1.w - va.w; s = fmaf(d, d, s);
            d = a2.x - vb.x; s = fmaf(d, d, s);
            d = a2.y - vb.y; s = fmaf(d, d, s);
            d = a2.z - vb.z; s = fmaf(d, d, s);
            d = a2.w - vb.w; s = fmaf(d, d, s);
            dist[a][jj] = s;
        }
    }

    // ---- butterfly reduce all 20 dot chains together ----
    #pragma unroll
    for (int off = 16; off; off >>= 1) {
        #pragma unroll
        for (int jj = 0; jj < CPWRP; jj++)
            down[jj] += __shfl_xor_sync(FULL, down[jj], off);
        #pragma unroll
        for (int a = 0; a < AG; a++)
            #pragma unroll
            for (int jj = 0; jj < CPWRP; jj++)
                dist[a][jj] += __shfl_xor_sync(FULL, dist[a][jj], off);
    }
    if (lane == 0) {
        #pragma unroll
        for (int jj = 0; jj < CPWRP; jj++) {
            const int oc = warp * CPWRP + jj;
            s_down[oc >> 4][oc & 15] = down[jj];
        }
    }
    __syncthreads();

    // ---- per-anchor positive masks + lane-compacted positive distances ----
    unsigned pm[AG]; float dpa[AG]; int nposA[AG];
    #pragma unroll
    for (int a = 0; a < AG; a++) {
        const unsigned m = __ballot_sync(FULL, (lane < W_) && (s_lab[a * W_ + lane] > 0.f));
        pm[a] = m; nposA[a] = __popc(m);
        int sl = __fns(m, 0, lane + 1);
        if (sl < 0 || sl > 31) sl = 0;
        dpa[a] = s_down[a][sl & 15];
    }

    // ---- pair phase: loop anchors, 4 register-resident distances each ----
    #pragma unroll
    for (int a = 0; a < AG; a++) {
        const int rowbase = (g * AG + a) * W_;
        const bool pl = (lane < nposA[a]);
        const float dp = dpa[a];
        float ts = 0.f; int hd = 0, ac = 0;
        float sn = 0.f, mv = INF_; int mi = NW_;
        float sp = 0.f, xv = -INF_; int xi = NW_;
        #pragma unroll
        for (int jj = 0; jj < CPWRP; jj++) {
            const int j = col0 + warp * CPWRP + jj;
            const float d = dist[a][jj];
            bool isNeg = true;
            if (ownChunk) {
                const int rel = j - rowbase;
                if ((unsigned)rel < (unsigned)W_) {
                    if (rel == 0) { isNeg = false; }
                    else if ((pm[a] >> rel) & 1u) {
                        isNeg = false;
                        sp += d;
                        if (d > xv) { xv = d; xi = j; }
                    }
                }
            }
            if (isNeg) {
                sn += d;
                if (d < mv) { mv = d; mi = j; }
                if (pl) {
                    const float v = dp - d + 1.0f;     // diff + MARGIN
                    ts += fmaxf(v, 0.f);
                    hd += (v > 1e-16f);
                    ac += (dp < d);
                }
            }
        }
        unsigned cb = (unsigned)hd | ((unsigned)ac << 16);
        #pragma unroll
        for (int off = 16; off; off >>= 1) {
            ts += __shfl_xor_sync(FULL, ts, off);
            cb += __shfl_xor_sync(FULL, cb, off);
        }
        if (lane == 0) {
            s_tsum[a][warp] = ts;  s_combo[a][warp] = cb;
            s_sn[a][warp] = sn;    s_minv[a][warp] = mv;  s_mini[a][warp] = mi;
            s_sp[a][warp] = sp;    s_maxv[a][warp] = xv;  s_maxi[a][warp] = xi;
        }
    }
    __syncthreads();

    // ---- block combine: warp a (<4) combines anchor a across 16 warps ----
    if (warp < AG) {
        const int a = warp;
        const bool v = (lane < NWARP);
        float    T  = v ? s_tsum[a][lane]  : 0.f;
        unsigned C  = v ? s_combo[a][lane] : 0u;
        float    SN = v ? s_sn[a][lane]    : 0.f;
        float    mV = v ? s_minv[a][lane]  : INF_;
        int      mI = v ? s_mini[a][lane]  : NW_;
        float    SP = v ? s_sp[a][lane]    : 0.f;
        float    XV = v ? s_maxv[a][lane]  : -INF_;
        int      XI = v ? s_maxi[a][lane]  : NW_;
        #pragma unroll
        for (int off = 16; off; off >>= 1) {
            T  += __shfl_xor_sync(FULL, T,  off);
            C  += __shfl_xor_sync(FULL, C,  off);
            SN += __shfl_xor_sync(FULL, SN, off);
            float nv = __shfl_xor_sync(FULL, mV, off);
            int   ni = __shfl_xor_sync(FULL, mI, off);
            if (nv < mV || (nv == mV && ni < mI)) { mV = nv; mI = ni; }
            float xv = __shfl_xor_sync(FULL, XV, off);
            int   xi = __shfl_xor_sync(FULL, XI, off);
            if (xv > XV || (xv == XV && xi < XI)) { XV = xv; XI = xi; }
            SP += __shfl_xor_sync(FULL, SP, off);
        }
        if (lane == 0) {
            const int ai = g * AG + a;
            g_tsum[ai][c] = T;   g_combo[ai][c] = C;
            g_sumNeg[ai][c] = SN; g_minV[ai][c] = mV; g_minI[ai][c] = mI;
            if (ownChunk) { g_sumPos[ai] = SP; g_maxV[ai] = XV; g_maxI[ai] = XI; }
        }
    }
    __syncthreads();

    if (tid == 0) {
        __threadfence();
        s_last = (atomicAdd(&g_count, 1) == GRID - 1);
    }
    __syncthreads();

    // ================= FINISH: single last block =================
    if (s_last) {
        __threadfence();   // acquire all blocks' partials

        // per-anchor outputs: thread a (<48) handles anchor a
        if (tid < N_) {
            const int a = tid;
            float sn = 0.f; int acc = 0;
            float mv = INF_; int mi = NW_;
            #pragma unroll
            for (int cc = 0; cc < NCH; cc++) {
                sn  += ((volatile float*)g_sumNeg[a])[cc];
                acc += (int)(((volatile unsigned*)g_combo[a])[cc] >> 16);
                float nv = ((volatile float*)g_minV[a])[cc];
                int   ni = ((volatile int*)g_minI[a])[cc];
                if (nv < mv || (nv == mv && ni < mi)) { mv = nv; mi = ni; }
            }
            const float sp  = ((volatile float*)g_sumPos)[a];
            const float MV2 = ((volatile float*)g_maxV)[a];
            const int   MI2 = ((volatile int*)g_maxI)[a];

            int np = 0, ex = 0, pr = 0;
            bool anch_pos = false;
            #pragma unroll
            for (int w = 0; w < W_; w++) {
                const bool isP = (lab[a * W_ + w] > 0.f);
                const int  col = a * W_ + w;
                np += isP;
                if (w == 0) anch_pos = isP;
                if (((w == 0) || isP) && col <= mi) ex++;
                if (isP && col <= MI2) pr++;
            }
            const int npext = np + (anch_pos ? 0 : 1);
            const float nn = (float)(NW_ - npext);
            const float npf = (float)np;
            const float npairs = npf * nn;

            out[1 + 0 * N_ + a] = MV2;                        // max_anchor2pos
            out[1 + 1 * N_ + a] = mv;                         // min_anchor2neg
            out[1 + 2 * N_ + a] = mv - MV2;                   // min_neg2pos
            out[1 + 3 * N_ + a] = (npf * sn - nn * sp) / npairs;  // avg_neg2pos
            out[1 + 4 * N_ + a] = (float)(mi - ex);           // neg_idx
            out[1 + 5 * N_ + a] = (float)(pr - 1);            // pos_idx
            out[1 + 6 * N_ + a] = (float)acc / npairs;        // accu_ratio
        }

        // global loss: warp 4, lane-strided over all 48*12 partials
        if (warp == 4) {
            const volatile float*    pt = &g_tsum[0][0];
            const volatile unsigned* pc = &g_combo[0][0];
            float s = 0.f, h = 0.f;
            for (int k = lane; k < N_ * NCH; k += 32) {
                s += pt[k];
                h += (float)(pc[k] & 0xffffu);
            }
            #pragma unroll
            for (int off = 16; off; off >>= 1) {
                s += __shfl_xor_sync(FULL, s, off);
                h += __shfl_xor_sync(FULL, h, off);
            }
            if (lane == 0) {
                out[0] = s / (h + 1e-16f);
                g_count = 0;   // reset for next graph replay
            }
        }
    }
}

extern "C" void kernel_launch(void* const* d_in, const int* in_sizes, int n_in,
                              void* d_out, int out_size) {
    const float* emb = (const float*)d_in[0];   // pred_embeddings [48,16,256]
    const float* lab = (const float*)d_in[1];   // pos_neg_label  [48,16]
    float* out = (float*)d_out;                 // 337 floats

    triplet_kernel<<<GRID, BLK>>>(emb, lab, out);
}

// round 9
// speedup vs baseline: 1.3092x; 1.3092x over previous
#include <cuda_runtime.h>

#define N_    48
#define W_    16
#define X_    256
#define NW_   (N_ * W_)
#define SPLIT 6
#define GRID  (N_ * SPLIT)       // 288
#define CPB   (NW_ / SPLIT)      // 128 columns per block
#define INF_  1e30f
#define NWARP 16
#define BLK   (NWARP * 32)       // 512 threads
#define FULL  0xffffffffu
#define CPW   (CPB / NWARP)      // 8 columns per warp

// Flat per-block partials
__device__ float    g_ltsum[GRID];
__device__ unsigned g_combo[GRID];     // hard | (accu<<16)
__device__ float    g_sumNeg[GRID];
__device__ float    g_minV[GRID];
__device__ int      g_minI[GRID];
// Per-anchor pos stats (single writer: the own-chunk block)
__device__ float    g_sumPos[N_];
__device__ float    g_maxV[N_];
__device__ int      g_maxI[N_];
__device__ int      g_count;           // zero-init; reset by finishing warp

__global__ void __launch_bounds__(BLK, 2) triplet_kernel(
    const float* __restrict__ emb,   // [N, W, X] f32
    const float* __restrict__ lab,   // [N, W]    f32 (0/1)
    float* __restrict__ out)         // [337]     f32
{
    const int bid  = blockIdx.x;
    const int i    = bid / SPLIT;          // anchor index
    const int c    = bid % SPLIT;          // column chunk
    const int col0 = c * CPB;
    const int tid  = threadIdx.x;
    const int lane = tid & 31;
    const int warp = tid >> 5;
    const bool hasOwn = (c == (i >> 3));   // own row (cols i*16..i*16+15) lives in chunk i/8

    __shared__ float    s_own[W_];
    __shared__ float    s_tsum[NWARP];
    __shared__ unsigned s_combo[NWARP];
    __shared__ float    s_sn[NWARP], s_minv[NWARP];
    __shared__ int      s_mini[NWARP];
    __shared__ float    s_sp[NWARP], s_maxv[NWARP];
    __shared__ int      s_maxi[NWARP];

    // labels straight to registers (per-warp redundant, L1-hit)
    const float labv = (lane < W_) ? lab[i * W_ + lane] : 0.f;

    // anchor row in registers
    const float4* a4 = reinterpret_cast<const float4*>(emb + (size_t)i * W_ * X_);
    const float4 aA = a4[lane];
    const float4 aB = a4[lane + 32];

    // ---- own-row distance: warp w computes own column w ----
    {
        const float4* f = reinterpret_cast<const float4*>(emb + (size_t)(i * W_ + warp) * X_);
        float4 va = f[lane], vb = f[lane + 32];
        float s = 0.f, d;
        d = aA.x - va.x; s = fmaf(d, d, s);
        d = aA.y - va.y; s = fmaf(d, d, s);
        d = aA.z - va.z; s = fmaf(d, d, s);
        d = aA.w - va.w; s = fmaf(d, d, s);
        d = aB.x - vb.x; s = fmaf(d, d, s);
        d = aB.y - vb.y; s = fmaf(d, d, s);
        d = aB.z - vb.z; s = fmaf(d, d, s);
        d = aB.w - vb.w; s = fmaf(d, d, s);
        #pragma unroll
        for (int off = 16; off; off >>= 1) s += __shfl_xor_sync(FULL, s, off);
        if (lane == 0) s_own[warp] = s;
    }

    // ---- 8 chunk-column distances, 2 batches of 4 ----
    float dcol[CPW];
    #pragma unroll
    for (int bt = 0; bt < 2; bt++) {
        float4 va[4], vb[4];
        #pragma unroll
        for (int u = 0; u < 4; u++) {
            const int j = col0 + warp + NWARP * (4 * bt + u);
            const float4* f = reinterpret_cast<const float4*>(emb + (size_t)j * X_);
            va[u] = f[lane]; vb[u] = f[lane + 32];
        }
        float s[4];
        #pragma unroll
        for (int u = 0; u < 4; u++) {
            float acc = 0.f, d;
            d = aA.x - va[u].x; acc = fmaf(d, d, acc);
            d = aA.y - va[u].y; acc = fmaf(d, d, acc);
            d = aA.z - va[u].z; acc = fmaf(d, d, acc);
            d = aA.w - va[u].w; acc = fmaf(d, d, acc);
            d = aB.x - vb[u].x; acc = fmaf(d, d, acc);
            d = aB.y - vb[u].y; acc = fmaf(d, d, acc);
            d = aB.z - vb[u].z; acc = fmaf(d, d, acc);
            d = aB.w - vb[u].w; acc = fmaf(d, d, acc);
            s[u] = acc;
        }
        #pragma unroll
        for (int off = 16; off; off >>= 1) {
            #pragma unroll
            for (int u = 0; u < 4; u++)
                s[u] += __shfl_xor_sync(FULL, s[u], off);
        }
        #pragma unroll
        for (int u = 0; u < 4; u++) dcol[4 * bt + u] = s[u];
    }
    __syncthreads();

    // ---- positive compaction: lane p gets distance of positive p ----
    const float ownv = (lane < W_) ? s_own[lane] : 0.f;
    const unsigned posmask = __ballot_sync(FULL, (lane < W_) && (labv > 0.f));
    const int npos = __popc(posmask);
    int srcl = __fns(posmask, 0, lane + 1);
    if (srcl < 0 || srcl > 31) srcl = 0;
    const float dp = __shfl_sync(FULL, ownv, srcl);
    const bool isPairLane = (lane < npos);

    // ---- pair phase over 8 register-resident distances ----
    float tsum = 0.f; int hard = 0, accu = 0;        // lane-parallel
    float sumNeg = 0.f;                              // uniform across lanes
    float minV = INF_; int minI = NW_;
    float sumPos = 0.f, maxV = -INF_; int maxI = NW_;

    if (hasOwn) {
        #pragma unroll
        for (int k = 0; k < CPW; k++) {
            const int j = col0 + warp + NWARP * k;
            const float d = dcol[k];
            const int rel = j - i * W_;
            const bool inRow  = ((unsigned)rel < (unsigned)W_);
            const bool isPos  = inRow && ((posmask >> (rel & 31)) & 1u);
            const bool isAnch = (rel == 0);
            if (isPos) {
                sumPos += d;
                if (d > maxV) { maxV = d; maxI = j; }
            } else if (!isAnch) {
                sumNeg += d;
                if (d < minV) { minV = d; minI = j; }
                if (isPairLane) {
                    float v = dp - d + 1.0f;          // diff + MARGIN
                    tsum += fmaxf(v, 0.f);
                    hard += (v > 1e-16f);
                    accu += (dp < d);
                }
            }
        }
    } else {
        // all 8 columns are negatives — branch-free
        #pragma unroll
        for (int k = 0; k < CPW; k++) {
            const int j = col0 + warp + NWARP * k;
            const float d = dcol[k];
            sumNeg += d;
            if (d < minV) { minV = d; minI = j; }
            if (isPairLane) {
                float v = dp - d + 1.0f;
                tsum += fmaxf(v, 0.f);
                hard += (v > 1e-16f);
                accu += (dp < d);
            }
        }
    }

    // ---- warp reduce lane-parallel quantities ----
    unsigned combo = (unsigned)hard | ((unsigned)accu << 16);
    #pragma unroll
    for (int off = 16; off; off >>= 1) {
        tsum  += __shfl_xor_sync(FULL, tsum,  off);
        combo += __shfl_xor_sync(FULL, combo, off);
    }
    if (lane == 0) {
        s_tsum[warp] = tsum;  s_combo[warp] = combo;
        s_sn[warp] = sumNeg;  s_minv[warp] = minV;  s_mini[warp] = minI;
        if (hasOwn) { s_sp[warp] = sumPos; s_maxv[warp] = maxV; s_maxi[warp] = maxI; }
    }
    __syncthreads();

    // ---- block combine + publish + finish, all in warp 0 ----
    if (warp == 0) {
        const bool v = (lane < NWARP);
        float    T  = v ? s_tsum[lane]  : 0.f;
        unsigned C  = v ? s_combo[lane] : 0u;
        float    SN = v ? s_sn[lane]    : 0.f;
        float    mV = v ? s_minv[lane]  : INF_;
        int      mI = v ? s_mini[lane]  : NW_;
        float    SP = (v && hasOwn) ? s_sp[lane]   : 0.f;
        float    MV = (v && hasOwn) ? s_maxv[lane] : -INF_;
        int      MI = (v && hasOwn) ? s_maxi[lane] : NW_;
        #pragma unroll
        for (int off = 16; off; off >>= 1) {
            T  += __shfl_xor_sync(FULL, T,  off);
            C  += __shfl_xor_sync(FULL, C,  off);
            SN += __shfl_xor_sync(FULL, SN, off);
            float nv = __shfl_xor_sync(FULL, mV, off);
            int   ni = __shfl_xor_sync(FULL, mI, off);
            if (nv < mV || (nv == mV && ni < mI)) { mV = nv; mI = ni; }
            float xv = __shfl_xor_sync(FULL, MV, off);
            int   xi = __shfl_xor_sync(FULL, MI, off);
            if (xv > MV || (xv == MV && xi < MI)) { MV = xv; MI = xi; }
            SP += __shfl_xor_sync(FULL, SP, off);
        }
        int last = 0;
        if (lane == 0) {
            g_ltsum[bid] = T;  g_combo[bid] = C;
            g_sumNeg[bid] = SN; g_minV[bid] = mV; g_minI[bid] = mI;
            if (hasOwn) { g_sumPos[i] = SP; g_maxV[i] = MV; g_maxI[i] = MI; }
            __threadfence();
            last = (atomicAdd(&g_count, 1) == GRID - 1);
        }
        last = __shfl_sync(FULL, last, 0);

        if (last) {
            __threadfence();   // acquire all blocks' partials

            // -- global loss: lane-strided fixed mapping over 288 partials --
            float s = 0.f, h = 0.f;
            for (int b = lane; b < GRID; b += 32) {
                s += ((volatile float*)g_ltsum)[b];
                h += (float)(((volatile unsigned*)g_combo)[b] & 0xffffu);
            }
            #pragma unroll
            for (int off = 16; off; off >>= 1) {
                s += __shfl_xor_sync(FULL, s, off);
                h += __shfl_xor_sync(FULL, h, off);
            }
            if (lane == 0) {
                out[0] = s / (h + 1e-16f);
                g_count = 0;   // reset for next graph replay
            }

            // -- per-anchor outputs: lane handles anchors lane, lane+32 --
            for (int a = lane; a < N_; a += 32) {
                float sn = 0.f; int acc = 0;
                float mv = INF_; int mi = NW_;
                #pragma unroll
                for (int cc = 0; cc < SPLIT; cc++) {
                    const int b = a * SPLIT + cc;
                    sn  += ((volatile float*)g_sumNeg)[b];
                    acc += (int)(((volatile unsigned*)g_combo)[b] >> 16);
                    float nv = ((volatile float*)g_minV)[b];
                    int   ni = ((volatile int*)g_minI)[b];
                    if (nv < mv || (nv == mv && ni < mi)) { mv = nv; mi = ni; }
                }
                const float sp  = ((volatile float*)g_sumPos)[a];
                const float MV2 = ((volatile float*)g_maxV)[a];
                const int   MI2 = ((volatile int*)g_maxI)[a];

                int np = 0, ex = 0, pr = 0;
                bool anch_pos = false;
                #pragma unroll
                for (int w = 0; w < W_; w++) {
                    const bool isP = (lab[a * W_ + w] > 0.f);
                    const int  col = a * W_ + w;
                    np += isP;
                    if (w == 0) anch_pos = isP;
                    if (((w == 0) || isP) && col <= mi) ex++;
                    if (isP && col <= MI2) pr++;
                }
                const int npext = np + (anch_pos ? 0 : 1);
                const float nn = (float)(NW_ - npext);
                const float npf = (float)np;
                const float npairs = npf * nn;

                out[1 + 0 * N_ + a] = MV2;                       // max_anchor2pos
                out[1 + 1 * N_ + a] = mv;                        // min_anchor2neg
                out[1 + 2 * N_ + a] = mv - MV2;                  // min_neg2pos
                out[1 + 3 * N_ + a] = (npf * sn - nn * sp) / npairs;  // avg_neg2pos
                out[1 + 4 * N_ + a] = (float)(mi - ex);          // neg_idx
                out[1 + 5 * N_ + a] = (float)(pr - 1);           // pos_idx
                out[1 + 6 * N_ + a] = (float)acc / npairs;       // accu_ratio
            }
        }
    }
}

extern "C" void kernel_launch(void* const* d_in, const int* in_sizes, int n_in,
                              void* d_out, int out_size) {
    const float* emb = (const float*)d_in[0];   // pred_embeddings [48,16,256]
    const float* lab = (const float*)d_in[1];   // pos_neg_label  [48,16]
    float* out = (float*)d_out;                 // 337 floats

    triplet_kernel<<<GRID, BLK>>>(emb, lab, out);
}